// round 7
// baseline (speedup 1.0000x reference)
#include <cuda_runtime.h>
#include <cstdint>

#define MLEN  16
#define DDIM  128
#define LNUM  26
#define KP    13
#define BPB   32      // words per block
#define NTHR  160     // 4 producer warps + 1 consumer warp
#define GRID  512
#define DSTR  34      // 8B-aligned rows, 2-way-max LDS.64 conflicts
#define ETSTR 14
#define RSTR  (MLEN * DDIM)   // float stride between consecutive words

__device__ float g_partials[GRID];
__device__ unsigned int g_count;

__shared__ uint2 Bp_s[1024];                  // bf16 B fragments (8KB)
__shared__ float Dring_s[4 * BPB * DSTR];     // 4-slot emission ring (17KB)
__shared__ float ET_s[LNUM * ETSTR * 2];
__shared__ float Tsm_s[LNUM * LNUM];
__shared__ int   flag_s;
__shared__ int   last_s;

// ---------------- helpers ----------------
static __device__ __forceinline__ unsigned long long pack2(float lo, float hi){
    unsigned long long r; asm("mov.b64 %0, {%1,%2};" : "=l"(r) : "f"(lo), "f"(hi)); return r;
}
static __device__ __forceinline__ void unpack2(unsigned long long v, float& lo, float& hi){
    asm("mov.b64 {%0,%1}, %2;" : "=f"(lo), "=f"(hi) : "l"(v));
}
static __device__ __forceinline__ void ffma2(unsigned long long& d, unsigned long long a, unsigned long long b){
    asm("fma.rn.f32x2 %0, %1, %2, %0;" : "+l"(d) : "l"(a), "l"(b));
}
static __device__ __forceinline__ uint32_t bfpack(float lo, float hi){
    uint32_t r; asm("cvt.rn.bf16x2.f32 %0, %1, %2;" : "=r"(r) : "f"(hi), "f"(lo)); return r;
}
static __device__ __forceinline__ void mma_bf16(float* d, uint32_t a0, uint32_t a1, uint32_t a2, uint32_t a3,
                                                uint32_t b0, uint32_t b1){
    asm volatile("mma.sync.aligned.m16n8k16.row.col.f32.bf16.bf16.f32 "
                 "{%0,%1,%2,%3}, {%4,%5,%6,%7}, {%8,%9}, {%0,%1,%2,%3};"
                 : "+f"(d[0]), "+f"(d[1]), "+f"(d[2]), "+f"(d[3])
                 : "r"(a0), "r"(a1), "r"(a2), "r"(a3), "r"(b0), "r"(b1));
}
static __device__ __forceinline__ void bar_sync(int id){
    asm volatile("bar.sync %0, 64;" :: "r"(id) : "memory");
}
static __device__ __forceinline__ void bar_arrive(int id){
    asm volatile("bar.arrive %0, 64;" :: "r"(id) : "memory");
}

__global__ __launch_bounds__(NTHR, 3)
void crf_main(const float* __restrict__ X, const void* __restrict__ Yv,
              const float* __restrict__ W, const float* __restrict__ T,
              float* __restrict__ out)
{
    const int tid  = threadIdx.x;
    const int wid  = tid >> 5;
    const int lane = tid & 31;
    const int b0   = blockIdx.x * BPB;

    // ---- init (all warps) ----
    for (int i = tid; i < 1024; i += NTHR) {
        int kt = i >> 7, rem = i & 127, nt = rem >> 5, ln = rem & 31;
        int n  = nt * 8 + (ln >> 2);
        int k0 = kt * 16 + (ln & 3) * 2;
        float w0 = 0.f, w1 = 0.f, w2 = 0.f, w3 = 0.f;
        if (n < LNUM) {
            w0 = W[n * DDIM + k0];     w1 = W[n * DDIM + k0 + 1];
            w2 = W[n * DDIM + k0 + 8]; w3 = W[n * DDIM + k0 + 9];
        }
        Bp_s[i] = make_uint2(bfpack(w0, w1), bfpack(w2, w3));
    }
    for (int i = tid; i < LNUM * ETSTR; i += NTHR) {
        int k = i / ETSTR, jp = i - k * ETSTR;
        float2 e = make_float2(0.f, 0.f);
        if (jp < KP) { e.x = __expf(T[k * LNUM + 2 * jp]); e.y = __expf(T[k * LNUM + 2 * jp + 1]); }
        ((float2*)ET_s)[i] = e;
    }
    for (int i = tid; i < LNUM * LNUM; i += NTHR) Tsm_s[i] = T[i];
    if (tid == 0) {
        const int* y32 = (const int*)Yv;
        int nz = 0;
        for (int i = 1; i < 128; i += 2) nz |= y32[i];
        flag_s = (nz == 0) ? 1 : 0;
    }
    __syncthreads();

    const int  rb    = blockIdx.x & 3;        // consumer warp id (rotates SMSP per block)
    const bool isrec = (wid == rb);

    if (!isrec) {
        // ================= PRODUCER =================
        const int g    = lane >> 2, t = lane & 3;
        const int slot = wid - (wid > rb ? 1 : 0);   // 0..3
        float* Dslot = Dring_s + slot * BPB * DSTR;

        #pragma unroll 1
        for (int i = 0; i < 4; i++) {
            const int s = slot + 4 * i;
            // ---- load + convert A fragments: rows g, g+8, g+16, g+24; 64 LDG.64 ----
            const float* xp = X + ((size_t)(b0 + g) * MLEN + s) * DDIM + t * 2;
            uint32_t A[4][8][2];
            #pragma unroll
            for (int kt = 0; kt < 8; kt++) {
                #pragma unroll
                for (int rr = 0; rr < 4; rr++) {
                    const float* p = xp + rr * 8 * RSTR + kt * 16;
                    float2 u = *(const float2*)(p);
                    float2 v = *(const float2*)(p + 8);
                    A[rr][kt][0] = bfpack(u.x, u.y);
                    A[rr][kt][1] = bfpack(v.x, v.y);
                }
            }
            // ---- 64 MMAs: 2 row-tiles x 4 n-tiles x 8 kt ----
            float acc[2][4][4];
            #pragma unroll
            for (int mt = 0; mt < 2; mt++)
                #pragma unroll
                for (int nt = 0; nt < 4; nt++)
                    #pragma unroll
                    for (int r = 0; r < 4; r++) acc[mt][nt][r] = 0.f;
            #pragma unroll
            for (int kt = 0; kt < 8; kt++) {
                const uint2* bp = Bp_s + kt * 128 + lane;
                uint2 bf[4] = { bp[0], bp[32], bp[64], bp[96] };
                #pragma unroll
                for (int mt = 0; mt < 2; mt++) {
                    uint32_t a0 = A[2 * mt][kt][0], a1 = A[2 * mt + 1][kt][0];
                    uint32_t a2 = A[2 * mt][kt][1], a3 = A[2 * mt + 1][kt][1];
                    #pragma unroll
                    for (int nt = 0; nt < 4; nt++)
                        mma_bf16(acc[mt][nt], a0, a1, a2, a3, bf[nt].x, bf[nt].y);
                }
            }
            // ---- wait slot free, publish, signal ----
            bar_sync(5 + slot);
            #pragma unroll
            for (int mt = 0; mt < 2; mt++) {
                int r0 = mt * 16 + g;
                #pragma unroll
                for (int nt = 0; nt < 4; nt++) {
                    int c = nt * 8 + t * 2;
                    *(float2*)&Dslot[r0 * DSTR + c]       = make_float2(acc[mt][nt][0], acc[mt][nt][1]);
                    *(float2*)&Dslot[(r0 + 8) * DSTR + c] = make_float2(acc[mt][nt][2], acc[mt][nt][3]);
                }
            }
            asm volatile("membar.cta;" ::: "memory");
            bar_arrive(1 + slot);
        }
        // idle until final reduction
    } else {
        // ================= CONSUMER (full 32 lanes, 1 word/lane) =================
        const bool is64 = flag_s != 0;
        const long long* Y64 = (const long long*)Yv;
        const int*       Y32 = (const int*)Yv;
        const int b = b0 + lane;

        // pre-arm all empty barriers
        #pragma unroll
        for (int g2 = 0; g2 < 4; g2++) bar_arrive(5 + g2);

        int ycur = is64 ? (int)Y64[(size_t)b * MLEN] : Y32[(size_t)b * MLEN];

        float a[LNUM];
        #pragma unroll
        for (int k = 0; k < LNUM; k++) a[k] = 1.0f;
        float node = 0.f, edge = 0.f, csc = 0.f, logz = 0.f;

        #pragma unroll 1
        for (int s = 0; s < MLEN; s++) {
            const int slot = s & 3;
            const float* Dw = Dring_s + slot * BPB * DSTR + lane * DSTR;

            int ynext = 0;
            if (s + 1 < MLEN)
                ynext = is64 ? (int)Y64[(size_t)b * MLEN + s + 1] : Y32[(size_t)b * MLEN + s + 1];

            bar_sync(1 + slot);

            float ef[LNUM];
            const float2* dr = (const float2*)Dw;
            #pragma unroll
            for (int p = 0; p < KP; p++) {
                float2 v = dr[p];
                ef[2 * p] = v.x; ef[2 * p + 1] = v.y;
            }
            node += Dw[ycur];   // dynamic scalar LDS

            if (s + 1 < MLEN) {
                edge += Tsm_s[ycur * LNUM + ynext];

                unsigned long long s2[KP];
                #pragma unroll
                for (int kp = 0; kp < KP; kp++) s2[kp] = 0ull;
                const ulonglong2* ETp = (const ulonglong2*)ET_s;
                #pragma unroll
                for (int k = 0; k < LNUM; k++) {
                    float e  = __expf(ef[k]);
                    float bk = (s == 0) ? e : a[k] * e;
                    unsigned long long bd = pack2(bk, bk);
                    const ulonglong2* er = ETp + k * (ETSTR / 2);
                    #pragma unroll
                    for (int j2 = 0; j2 < 7; j2++) {
                        ulonglong2 e2 = er[j2];
                        ffma2(s2[2 * j2], bd, e2.x);
                        if (2 * j2 + 1 < KP) ffma2(s2[2 * j2 + 1], bd, e2.y);
                    }
                }
                float sv[LNUM];
                #pragma unroll
                for (int kp = 0; kp < KP; kp++) unpack2(s2[kp], sv[2 * kp], sv[2 * kp + 1]);
                float m = sv[0];
                #pragma unroll
                for (int k = 1; k < LNUM; k++) m = fmaxf(m, sv[k]);
                float inv = __fdividef(1.0f, m);
                #pragma unroll
                for (int k = 0; k < LNUM; k++) a[k] = sv[k] * inv;
                csc += __logf(m);
                ycur = ynext;
            } else {
                float ssum = 0.f;
                #pragma unroll
                for (int k = 0; k < LNUM; k++) ssum += a[k] * __expf(ef[k]);
                logz = csc + __logf(ssum);
            }
            bar_arrive(5 + slot);
        }

        // per-warp reduce over 32 words
        float val = logz - node - edge;
        #pragma unroll
        for (int o = 16; o; o >>= 1) val += __shfl_xor_sync(0xffffffffu, val, o);
        if (lane == 0) g_partials[blockIdx.x] = val;
    }

    __syncthreads();   // consumer's g_partials write done before tid0 signals

    if (tid == 0) {
        __threadfence();
        unsigned int old = atomicAdd(&g_count, 1u);
        last_s = (old == (unsigned)(gridDim.x - 1)) ? 1 : 0;
    }
    __syncthreads();
    if (last_s && tid < 32) {
        __threadfence();
        const volatile float* gp = (const volatile float*)g_partials;
        float v = 0.f;
        #pragma unroll
        for (int i = 0; i < GRID / 32; i++) v += gp[lane + i * 32];  // fixed order
        #pragma unroll
        for (int o = 16; o; o >>= 1) v += __shfl_xor_sync(0xffffffffu, v, o);
        if (lane == 0) { out[0] = v; g_count = 0; }
    }
}

extern "C" void kernel_launch(void* const* d_in, const int* in_sizes, int n_in,
                              void* d_out, int out_size)
{
    const float* X = (const float*)d_in[0];
    const void*  Y = d_in[1];
    const float* W = (const float*)d_in[2];
    const float* T = (const float*)d_in[3];

    crf_main<<<GRID, NTHR>>>(X, Y, W, T, (float*)d_out);
}

// round 8
// speedup vs baseline: 1.0033x; 1.0033x over previous
#include <cuda_runtime.h>
#include <cstdint>

#define MLEN  16
#define DDIM  128
#define LNUM  26
#define KP    13
#define BPB   32      // words per block
#define NTHR  160     // 4 producer warps + 1 consumer warp
#define GRID  512
#define DSTR  34      // 8B-aligned rows, 2-way-max LDS.64 conflicts
#define ETSTR 14
#define RSTR  (MLEN * DDIM)   // float stride between consecutive words

__device__ float g_partials[GRID];
__device__ unsigned int g_count;

__shared__ uint2 Bp_s[1024];                  // bf16 B fragments (8KB)
__shared__ float Dring_s[4 * BPB * DSTR];     // 4-slot emission ring (17KB)
__shared__ float ET_s[LNUM * ETSTR * 2];
__shared__ float Tsm_s[LNUM * LNUM];
__shared__ int   flag_s;
__shared__ int   last_s;

// ---------------- helpers ----------------
static __device__ __forceinline__ unsigned long long pack2(float lo, float hi){
    unsigned long long r; asm("mov.b64 %0, {%1,%2};" : "=l"(r) : "f"(lo), "f"(hi)); return r;
}
static __device__ __forceinline__ void unpack2(unsigned long long v, float& lo, float& hi){
    asm("mov.b64 {%0,%1}, %2;" : "=f"(lo), "=f"(hi) : "l"(v));
}
static __device__ __forceinline__ void ffma2(unsigned long long& d, unsigned long long a, unsigned long long b){
    asm("fma.rn.f32x2 %0, %1, %2, %0;" : "+l"(d) : "l"(a), "l"(b));
}
static __device__ __forceinline__ uint32_t bfpack(float lo, float hi){
    uint32_t r; asm("cvt.rn.bf16x2.f32 %0, %1, %2;" : "=r"(r) : "f"(hi), "f"(lo)); return r;
}
static __device__ __forceinline__ void mma_bf16(float* d, uint32_t a0, uint32_t a1, uint32_t a2, uint32_t a3,
                                                uint32_t b0, uint32_t b1){
    asm volatile("mma.sync.aligned.m16n8k16.row.col.f32.bf16.bf16.f32 "
                 "{%0,%1,%2,%3}, {%4,%5,%6,%7}, {%8,%9}, {%0,%1,%2,%3};"
                 : "+f"(d[0]), "+f"(d[1]), "+f"(d[2]), "+f"(d[3])
                 : "r"(a0), "r"(a1), "r"(a2), "r"(a3), "r"(b0), "r"(b1));
}
static __device__ __forceinline__ void bar_sync(int id){
    asm volatile("bar.sync %0, 64;" :: "r"(id) : "memory");
}
static __device__ __forceinline__ void bar_arrive(int id){
    asm volatile("bar.arrive %0, 64;" :: "r"(id) : "memory");
}

__global__ __launch_bounds__(NTHR, 3)
void crf_main(const float* __restrict__ X, const void* __restrict__ Yv,
              const float* __restrict__ W, const float* __restrict__ T,
              float* __restrict__ out)
{
    const int tid  = threadIdx.x;
    const int wid  = tid >> 5;
    const int lane = tid & 31;
    const int b0   = blockIdx.x * BPB;

    // ---- init (all warps) ----
    for (int i = tid; i < 1024; i += NTHR) {
        int kt = i >> 7, rem = i & 127, nt = rem >> 5, ln = rem & 31;
        int n  = nt * 8 + (ln >> 2);
        int k0 = kt * 16 + (ln & 3) * 2;
        float w0 = 0.f, w1 = 0.f, w2 = 0.f, w3 = 0.f;
        if (n < LNUM) {
            w0 = W[n * DDIM + k0];     w1 = W[n * DDIM + k0 + 1];
            w2 = W[n * DDIM + k0 + 8]; w3 = W[n * DDIM + k0 + 9];
        }
        Bp_s[i] = make_uint2(bfpack(w0, w1), bfpack(w2, w3));
    }
    for (int i = tid; i < LNUM * ETSTR; i += NTHR) {
        int k = i / ETSTR, jp = i - k * ETSTR;
        float2 e = make_float2(0.f, 0.f);
        if (jp < KP) { e.x = __expf(T[k * LNUM + 2 * jp]); e.y = __expf(T[k * LNUM + 2 * jp + 1]); }
        ((float2*)ET_s)[i] = e;
    }
    for (int i = tid; i < LNUM * LNUM; i += NTHR) Tsm_s[i] = T[i];
    if (tid == 0) {
        const int* y32 = (const int*)Yv;
        int nz = 0;
        for (int i = 1; i < 128; i += 2) nz |= y32[i];
        flag_s = (nz == 0) ? 1 : 0;
    }
    __syncthreads();

    const int  rb    = blockIdx.x & 3;        // consumer warp id (rotates SMSP per block)
    const bool isrec = (wid == rb);

    if (!isrec) {
        // ================= PRODUCER =================
        const int g    = lane >> 2, t = lane & 3;
        const int slot = wid - (wid > rb ? 1 : 0);   // 0..3
        float* Dslot = Dring_s + slot * BPB * DSTR;

        #pragma unroll 1
        for (int i = 0; i < 4; i++) {
            const int s = slot + 4 * i;
            // ---- load + convert A fragments: rows g, g+8, g+16, g+24; 64 LDG.64 ----
            const float* xp = X + ((size_t)(b0 + g) * MLEN + s) * DDIM + t * 2;
            uint32_t A[4][8][2];
            #pragma unroll
            for (int kt = 0; kt < 8; kt++) {
                #pragma unroll
                for (int rr = 0; rr < 4; rr++) {
                    const float* p = xp + rr * 8 * RSTR + kt * 16;
                    float2 u = *(const float2*)(p);
                    float2 v = *(const float2*)(p + 8);
                    A[rr][kt][0] = bfpack(u.x, u.y);
                    A[rr][kt][1] = bfpack(v.x, v.y);
                }
            }
            // ---- 64 MMAs: 2 row-tiles x 4 n-tiles x 8 kt ----
            float acc[2][4][4];
            #pragma unroll
            for (int mt = 0; mt < 2; mt++)
                #pragma unroll
                for (int nt = 0; nt < 4; nt++)
                    #pragma unroll
                    for (int r = 0; r < 4; r++) acc[mt][nt][r] = 0.f;
            #pragma unroll
            for (int kt = 0; kt < 8; kt++) {
                const uint2* bp = Bp_s + kt * 128 + lane;
                uint2 bf[4] = { bp[0], bp[32], bp[64], bp[96] };
                #pragma unroll
                for (int mt = 0; mt < 2; mt++) {
                    uint32_t a0 = A[2 * mt][kt][0], a1 = A[2 * mt + 1][kt][0];
                    uint32_t a2 = A[2 * mt][kt][1], a3 = A[2 * mt + 1][kt][1];
                    #pragma unroll
                    for (int nt = 0; nt < 4; nt++)
                        mma_bf16(acc[mt][nt], a0, a1, a2, a3, bf[nt].x, bf[nt].y);
                }
            }
            // ---- wait slot free, publish, signal ----
            bar_sync(5 + slot);
            #pragma unroll
            for (int mt = 0; mt < 2; mt++) {
                int r0 = mt * 16 + g;
                #pragma unroll
                for (int nt = 0; nt < 4; nt++) {
                    int c = nt * 8 + t * 2;
                    *(float2*)&Dslot[r0 * DSTR + c]       = make_float2(acc[mt][nt][0], acc[mt][nt][1]);
                    *(float2*)&Dslot[(r0 + 8) * DSTR + c] = make_float2(acc[mt][nt][2], acc[mt][nt][3]);
                }
            }
            asm volatile("membar.cta;" ::: "memory");
            bar_arrive(1 + slot);
        }
        // idle until final reduction
    } else {
        // ================= CONSUMER (full 32 lanes, 1 word/lane) =================
        const bool is64 = flag_s != 0;
        const long long* Y64 = (const long long*)Yv;
        const int*       Y32 = (const int*)Yv;
        const int b = b0 + lane;

        // pre-arm all empty barriers
        #pragma unroll
        for (int g2 = 0; g2 < 4; g2++) bar_arrive(5 + g2);

        int ycur = is64 ? (int)Y64[(size_t)b * MLEN] : Y32[(size_t)b * MLEN];

        float a[LNUM];
        #pragma unroll
        for (int k = 0; k < LNUM; k++) a[k] = 1.0f;
        float node = 0.f, edge = 0.f, csc = 0.f, logz = 0.f;

        #pragma unroll 1
        for (int s = 0; s < MLEN; s++) {
            const int slot = s & 3;
            const float* Dw = Dring_s + slot * BPB * DSTR + lane * DSTR;

            int ynext = 0;
            if (s + 1 < MLEN)
                ynext = is64 ? (int)Y64[(size_t)b * MLEN + s + 1] : Y32[(size_t)b * MLEN + s + 1];

            bar_sync(1 + slot);

            float ef[LNUM];
            const float2* dr = (const float2*)Dw;
            #pragma unroll
            for (int p = 0; p < KP; p++) {
                float2 v = dr[p];
                ef[2 * p] = v.x; ef[2 * p + 1] = v.y;
            }
            node += Dw[ycur];   // dynamic scalar LDS

            if (s + 1 < MLEN) {
                edge += Tsm_s[ycur * LNUM + ynext];

                unsigned long long s2[KP];
                #pragma unroll
                for (int kp = 0; kp < KP; kp++) s2[kp] = 0ull;
                const ulonglong2* ETp = (const ulonglong2*)ET_s;
                #pragma unroll
                for (int k = 0; k < LNUM; k++) {
                    float e  = __expf(ef[k]);
                    float bk = (s == 0) ? e : a[k] * e;
                    unsigned long long bd = pack2(bk, bk);
                    const ulonglong2* er = ETp + k * (ETSTR / 2);
                    #pragma unroll
                    for (int j2 = 0; j2 < 7; j2++) {
                        ulonglong2 e2 = er[j2];
                        ffma2(s2[2 * j2], bd, e2.x);
                        if (2 * j2 + 1 < KP) ffma2(s2[2 * j2 + 1], bd, e2.y);
                    }
                }
                float sv[LNUM];
                #pragma unroll
                for (int kp = 0; kp < KP; kp++) unpack2(s2[kp], sv[2 * kp], sv[2 * kp + 1]);
                float m = sv[0];
                #pragma unroll
                for (int k = 1; k < LNUM; k++) m = fmaxf(m, sv[k]);
                float inv = __fdividef(1.0f, m);
                #pragma unroll
                for (int k = 0; k < LNUM; k++) a[k] = sv[k] * inv;
                csc += __logf(m);
                ycur = ynext;
            } else {
                float ssum = 0.f;
                #pragma unroll
                for (int k = 0; k < LNUM; k++) ssum += a[k] * __expf(ef[k]);
                logz = csc + __logf(ssum);
            }
            bar_arrive(5 + slot);
        }

        // per-warp reduce over 32 words
        float val = logz - node - edge;
        #pragma unroll
        for (int o = 16; o; o >>= 1) val += __shfl_xor_sync(0xffffffffu, val, o);
        if (lane == 0) g_partials[blockIdx.x] = val;
    }

    __syncthreads();   // consumer's g_partials write done before tid0 signals

    if (tid == 0) {
        __threadfence();
        unsigned int old = atomicAdd(&g_count, 1u);
        last_s = (old == (unsigned)(gridDim.x - 1)) ? 1 : 0;
    }
    __syncthreads();
    if (last_s && tid < 32) {
        __threadfence();
        const volatile float* gp = (const volatile float*)g_partials;
        float v = 0.f;
        #pragma unroll
        for (int i = 0; i < GRID / 32; i++) v += gp[lane + i * 32];  // fixed order
        #pragma unroll
        for (int o = 16; o; o >>= 1) v += __shfl_xor_sync(0xffffffffu, v, o);
        if (lane == 0) { out[0] = v; g_count = 0; }
    }
}

extern "C" void kernel_launch(void* const* d_in, const int* in_sizes, int n_in,
                              void* d_out, int out_size)
{
    const float* X = (const float*)d_in[0];
    const void*  Y = d_in[1];
    const float* W = (const float*)d_in[2];
    const float* T = (const float*)d_in[3];

    crf_main<<<GRID, NTHR>>>(X, Y, W, T, (float*)d_out);
}

// round 9
// speedup vs baseline: 1.5239x; 1.5189x over previous
#include <cuda_runtime.h>
#include <cstdint>

#define MLEN  16
#define DDIM  128
#define LNUM  26
#define KP    13
#define BPB   64      // words per block
#define NTHR  128     // 4 warps
#define GRID  256
#define XSTR  136     // padded floats per X row (conflict-free float2 fragment loads)
#define DSTR  36
#define ETSTR 14
#define NBUF  2

// ---- smem layout (float indices) ----
#define XS_F    (BPB * XSTR)                  // 8704 per buffer
#define XOFF(b) ((b) * XS_F)
#define BPOFF   (NBUF * XS_F)                 // 17408: Bp 1024 uint2 = 2048 floats
#define DOFF    (BPOFF + 2048)                // 19456: D 64*36 = 2304
#define ETOFF   (DOFF + BPB * DSTR)           // 21760: expT 728
#define TSOFF   (ETOFF + LNUM * ETSTR * 2)    // 22488: T 676
#define YSOFF   (TSOFF + LNUM * LNUM)         // 23164: Y labels 64*16 ints = 1024
#define REDOFF  (YSOFF + BPB * MLEN)          // 24188
#define FLGOFF  (REDOFF + 4)                  // 24192
#define SMEM_F  (FLGOFF + 4)
#define SMEM_BYTES (SMEM_F * 4)               // ~96.8 KB -> 2 blocks/SM

__device__ float g_partials[GRID];
__device__ unsigned int g_count;

// ---------------- helpers ----------------
static __device__ __forceinline__ unsigned long long pack2(float lo, float hi){
    unsigned long long r; asm("mov.b64 %0, {%1,%2};" : "=l"(r) : "f"(lo), "f"(hi)); return r;
}
static __device__ __forceinline__ void unpack2(unsigned long long v, float& lo, float& hi){
    asm("mov.b64 {%0,%1}, %2;" : "=f"(lo), "=f"(hi) : "l"(v));
}
static __device__ __forceinline__ void ffma2(unsigned long long& d, unsigned long long a, unsigned long long b){
    asm("fma.rn.f32x2 %0, %1, %2, %0;" : "+l"(d) : "l"(a), "l"(b));
}
static __device__ __forceinline__ void cp16(uint32_t dst, const void* src){
    asm volatile("cp.async.cg.shared.global [%0], [%1], 16;" :: "r"(dst), "l"(src));
}
static __device__ __forceinline__ uint32_t bfpack(float lo, float hi){
    uint32_t r; asm("cvt.rn.bf16x2.f32 %0, %1, %2;" : "=r"(r) : "f"(hi), "f"(lo)); return r;
}
static __device__ __forceinline__ void mma_bf16(float* d, uint32_t a0, uint32_t a1, uint32_t a2, uint32_t a3,
                                                uint32_t b0, uint32_t b1){
    asm volatile("mma.sync.aligned.m16n8k16.row.col.f32.bf16.bf16.f32 "
                 "{%0,%1,%2,%3}, {%4,%5,%6,%7}, {%8,%9}, {%0,%1,%2,%3};"
                 : "+f"(d[0]), "+f"(d[1]), "+f"(d[2]), "+f"(d[3])
                 : "r"(a0), "r"(a1), "r"(a2), "r"(a3), "r"(b0), "r"(b1));
}

static __device__ __forceinline__ void stage_x(float* sm, const float4* X4, int b0, int s, int buf, int tid){
    uint32_t base = (uint32_t)__cvta_generic_to_shared(sm + XOFF(buf));
    #pragma unroll 4
    for (int v = tid; v < BPB * 32; v += NTHR) {
        int i = v >> 5, f = v & 31;
        uint32_t dst = base + (uint32_t)(i * XSTR + f * 4) * 4u;
        cp16(dst, X4 + ((size_t)(b0 + i) * MLEN + s) * 32 + f);
    }
    asm volatile("cp.async.commit_group;" ::: "memory");
}

__global__ __launch_bounds__(NTHR, 2)
void crf_main(const float* __restrict__ X, const void* __restrict__ Yv,
              const float* __restrict__ W, const float* __restrict__ T,
              float* __restrict__ out)
{
    extern __shared__ float sm[];
    const int tid  = threadIdx.x;
    const int wid  = tid >> 5;
    const int lane = tid & 31;
    const int g    = lane >> 2, t = lane & 3;
    const int b0   = blockIdx.x * BPB;
    const float4* X4 = (const float4*)X;

    stage_x(sm, X4, b0, 0, 0, tid);
    stage_x(sm, X4, b0, 1, 1, tid);

    // ---- prepack bf16 B fragments ----
    uint2* Bp = (uint2*)(sm + BPOFF);
    for (int i = tid; i < 8 * 4 * 32; i += NTHR) {
        int kt = i >> 7, rem = i & 127, nt = rem >> 5, ln = rem & 31;
        int n  = nt * 8 + (ln >> 2);
        int k0 = kt * 16 + (ln & 3) * 2;
        float w0 = 0.f, w1 = 0.f, w2 = 0.f, w3 = 0.f;
        if (n < LNUM) {
            w0 = W[n * DDIM + k0];     w1 = W[n * DDIM + k0 + 1];
            w2 = W[n * DDIM + k0 + 8]; w3 = W[n * DDIM + k0 + 9];
        }
        Bp[i] = make_uint2(bfpack(w0, w1), bfpack(w2, w3));
    }
    float* ET  = sm + ETOFF;
    float* Tsm = sm + TSOFF;
    for (int i = tid; i < LNUM * ETSTR; i += NTHR) {
        int k = i / ETSTR, jp = i - k * ETSTR;
        float2 e = make_float2(0.f, 0.f);
        if (jp < KP) { e.x = __expf(T[k * LNUM + 2 * jp]); e.y = __expf(T[k * LNUM + 2 * jp + 1]); }
        ((float2*)ET)[i] = e;
    }
    for (int i = tid; i < LNUM * LNUM; i += NTHR) Tsm[i] = T[i];
    if (tid == 0) {
        const int* y32 = (const int*)Yv;
        int nz = 0;
        for (int i = 1; i < 128; i += 2) nz |= y32[i];
        ((int*)sm)[FLGOFF] = (nz == 0) ? 1 : 0;
    }
    __syncthreads();

    // ---- preload Y labels for this block's 64 words into smem ----
    {
        const bool is64i = ((int*)sm)[FLGOFF] != 0;
        int* Ys = (int*)sm + YSOFF;
        if (is64i) {
            const long long* Y64 = (const long long*)Yv;
            #pragma unroll
            for (int u = 0; u < BPB * MLEN / NTHR; u++) {
                int i = tid + u * NTHR;
                Ys[i] = (int)Y64[(size_t)b0 * MLEN + i];
            }
        } else {
            const int* Y32 = (const int*)Yv;
            #pragma unroll
            for (int u = 0; u < BPB * MLEN / NTHR; u++) {
                int i = tid + u * NTHR;
                Ys[i] = Y32[(size_t)b0 * MLEN + i];
            }
        }
    }
    __syncthreads();

    // recurrence ownership: warps [2*rot, 2*rot+1], rotated per block for SMSP balance
    const int  rot   = blockIdx.x & 1;
    const bool owner = (wid >> 1) == rot;
    const int  w     = tid & 63;              // word index for owner threads
    const int* Ys    = (int*)sm + YSOFF;

    int ycur = 0;
    if (owner) ycur = Ys[w * MLEN];

    float a[LNUM];
    #pragma unroll
    for (int k = 0; k < LNUM; k++) a[k] = 1.0f;
    float node = 0.f, edge = 0.f, csc = 0.f, logz = 0.f;

    float* Dsm = sm + DOFF;

    for (int s = 0; s < MLEN; s++) {
        const int buf = s & 1;

        if (s < MLEN - 1) asm volatile("cp.async.wait_group 1;" ::: "memory");
        else              asm volatile("cp.async.wait_group 0;" ::: "memory");
        __syncthreads();   // X(s) visible; D(s-1) fully consumed

        // ---- GEMM: warp wid computes rows [wid*16, wid*16+16) x N=32, K=128 ----
        {
            float acc[4][4];
            #pragma unroll
            for (int nt = 0; nt < 4; nt++)
                #pragma unroll
                for (int r = 0; r < 4; r++) acc[nt][r] = 0.f;

            const float* Xb = sm + XOFF(buf) + (wid * 16) * XSTR;
            #pragma unroll
            for (int kt = 0; kt < 8; kt++) {
                const float* xp = Xb + g * XSTR + kt * 16 + t * 2;
                float2 v0 = *(const float2*)(xp);
                float2 v2 = *(const float2*)(xp + 8);
                float2 v1 = *(const float2*)(xp + 8 * XSTR);
                float2 v3 = *(const float2*)(xp + 8 * XSTR + 8);
                uint32_t a0 = bfpack(v0.x, v0.y);
                uint32_t a1 = bfpack(v1.x, v1.y);
                uint32_t a2 = bfpack(v2.x, v2.y);
                uint32_t a3 = bfpack(v3.x, v3.y);
                const uint2* bp = Bp + (kt * 4) * 32 + lane;
                uint2 bf0 = bp[0];
                uint2 bf1 = bp[32];
                uint2 bf2 = bp[64];
                uint2 bf3 = bp[96];
                mma_bf16(acc[0], a0, a1, a2, a3, bf0.x, bf0.y);
                mma_bf16(acc[1], a0, a1, a2, a3, bf1.x, bf1.y);
                mma_bf16(acc[2], a0, a1, a2, a3, bf2.x, bf2.y);
                mma_bf16(acc[3], a0, a1, a2, a3, bf3.x, bf3.y);
            }
            int r0 = wid * 16 + g;
            #pragma unroll
            for (int nt = 0; nt < 4; nt++) {
                int c = nt * 8 + t * 2;
                *(float2*)&Dsm[r0 * DSTR + c]       = make_float2(acc[nt][0], acc[nt][1]);
                *(float2*)&Dsm[(r0 + 8) * DSTR + c] = make_float2(acc[nt][2], acc[nt][3]);
            }
        }
        __syncthreads();   // D(s) visible; X(buf) fully consumed

        if (s + 2 < MLEN) stage_x(sm, X4, b0, s + 2, buf, tid);

        // ---- recurrence: rotated warp pair, one word per thread ----
        if (owner) {
            float ef[LNUM];
            const float4* dr = (const float4*)&Dsm[w * DSTR];
            #pragma unroll
            for (int q = 0; q < 6; q++) {
                float4 v = dr[q];
                ef[4 * q] = v.x; ef[4 * q + 1] = v.y; ef[4 * q + 2] = v.z; ef[4 * q + 3] = v.w;
            }
            { float2 v = *(const float2*)&Dsm[w * DSTR + 24]; ef[24] = v.x; ef[25] = v.y; }

            node += Dsm[w * DSTR + ycur];   // dynamic LDS instead of 26-way select

            if (s + 1 < MLEN) {
                int ynext = Ys[w * MLEN + s + 1];
                edge += Tsm[ycur * LNUM + ynext];

                unsigned long long s2[KP];
                #pragma unroll
                for (int kp = 0; kp < KP; kp++) s2[kp] = 0ull;
                const ulonglong2* ETp = (const ulonglong2*)ET;
                #pragma unroll
                for (int k = 0; k < LNUM; k++) {
                    float e  = __expf(ef[k]);
                    float bk = (s == 0) ? e : a[k] * e;
                    unsigned long long bd = pack2(bk, bk);
                    const ulonglong2* er = ETp + k * (ETSTR / 2);
                    #pragma unroll
                    for (int j2 = 0; j2 < 7; j2++) {
                        ulonglong2 e2 = er[j2];
                        ffma2(s2[2 * j2], bd, e2.x);
                        if (2 * j2 + 1 < KP) ffma2(s2[2 * j2 + 1], bd, e2.y);
                    }
                }
                float sv[LNUM];
                #pragma unroll
                for (int kp = 0; kp < KP; kp++) unpack2(s2[kp], sv[2 * kp], sv[2 * kp + 1]);
                float m = sv[0];
                #pragma unroll
                for (int k = 1; k < LNUM; k++) m = fmaxf(m, sv[k]);
                float inv = __fdividef(1.0f, m);
                #pragma unroll
                for (int k = 0; k < LNUM; k++) a[k] = sv[k] * inv;
                csc += __logf(m);
                ycur = ynext;
            } else {
                float ssum = 0.f;
                #pragma unroll
                for (int k = 0; k < LNUM; k++) ssum += a[k] * __expf(ef[k]);
                logz = csc + __logf(ssum);
            }
        }
    }

    // ---- block reduction ----
    float val = owner ? (logz - node - edge) : 0.f;
    #pragma unroll
    for (int o = 16; o; o >>= 1) val += __shfl_xor_sync(0xffffffffu, val, o);
    float* red = sm + REDOFF;
    if (lane == 0) red[wid] = val;
    __syncthreads();

    __shared__ int s_last;
    if (tid == 0) {
        g_partials[blockIdx.x] = red[0] + red[1] + red[2] + red[3];
        __threadfence();
        unsigned int old = atomicAdd(&g_count, 1u);
        s_last = (old == (unsigned)(gridDim.x - 1)) ? 1 : 0;
    }
    __syncthreads();
    if (s_last && tid < 32) {
        __threadfence();
        const volatile float* gp = (const volatile float*)g_partials;
        float v = 0.f;
        #pragma unroll
        for (int i = 0; i < GRID / 32; i++) v += gp[lane + i * 32];  // fixed order
        #pragma unroll
        for (int o = 16; o; o >>= 1) v += __shfl_xor_sync(0xffffffffu, v, o);
        if (lane == 0) { out[0] = v; g_count = 0; }
    }
}

extern "C" void kernel_launch(void* const* d_in, const int* in_sizes, int n_in,
                              void* d_out, int out_size)
{
    const float* X = (const float*)d_in[0];
    const void*  Y = d_in[1];
    const float* W = (const float*)d_in[2];
    const float* T = (const float*)d_in[3];

    cudaFuncSetAttribute(crf_main, cudaFuncAttributeMaxDynamicSharedMemorySize, SMEM_BYTES);
    crf_main<<<GRID, NTHR, SMEM_BYTES>>>(X, Y, W, T, (float*)d_out);
}

// round 10
// speedup vs baseline: 1.9135x; 1.2557x over previous
#include <cuda_runtime.h>
#include <cstdint>

#define MLEN  16
#define DDIM  128
#define LNUM  26
#define BPB   64      // words per block
#define NTHR  128     // 4 warps
#define GRID  256
#define XSTR  136     // padded floats per X row
#define NBUF  2

// ---- smem layout (float indices) ----
#define XS_F    (BPB * XSTR)                 // 8704 per buffer
#define XOFF(b) ((b) * XS_F)
#define BPOFF   (NBUF * XS_F)                // 17408: Bp 1024 uint2 = 2048 floats
#define TSOFF   (BPOFF + 2048)               // 19456: raw T 676
#define YSOFF   (TSOFF + LNUM * LNUM)        // 20132: Y labels 64*16 ints
#define REDOFF  (YSOFF + BPB * MLEN)         // 21156
#define FLGOFF  (REDOFF + 4)
#define SMEM_F  (FLGOFF + 4)
#define SMEM_BYTES (SMEM_F * 4)              // ~84.7 KB -> 2 blocks/SM

__device__ float g_partials[GRID];
__device__ unsigned int g_count;

static __device__ __forceinline__ void cp16(uint32_t dst, const void* src){
    asm volatile("cp.async.cg.shared.global [%0], [%1], 16;" :: "r"(dst), "l"(src));
}
static __device__ __forceinline__ uint32_t bfpack(float lo, float hi){
    uint32_t r; asm("cvt.rn.bf16x2.f32 %0, %1, %2;" : "=r"(r) : "f"(hi), "f"(lo)); return r;
}
static __device__ __forceinline__ void mma_bf16(float* d, uint32_t a0, uint32_t a1, uint32_t a2, uint32_t a3,
                                                uint32_t b0, uint32_t b1){
    asm volatile("mma.sync.aligned.m16n8k16.row.col.f32.bf16.bf16.f32 "
                 "{%0,%1,%2,%3}, {%4,%5,%6,%7}, {%8,%9}, {%0,%1,%2,%3};"
                 : "+f"(d[0]), "+f"(d[1]), "+f"(d[2]), "+f"(d[3])
                 : "r"(a0), "r"(a1), "r"(a2), "r"(a3), "r"(b0), "r"(b1));
}

static __device__ __forceinline__ void stage_x(float* sm, const float4* X4, int b0, int s, int buf, int tid){
    uint32_t base = (uint32_t)__cvta_generic_to_shared(sm + XOFF(buf));
    #pragma unroll 4
    for (int v = tid; v < BPB * 32; v += NTHR) {
        int i = v >> 5, f = v & 31;
        uint32_t dst = base + (uint32_t)(i * XSTR + f * 4) * 4u;
        cp16(dst, X4 + ((size_t)(b0 + i) * MLEN + s) * 32 + f);
    }
    asm volatile("cp.async.commit_group;" ::: "memory");
}

__global__ __launch_bounds__(NTHR, 2)
void crf_main(const float* __restrict__ X, const void* __restrict__ Yv,
              const float* __restrict__ W, const float* __restrict__ T,
              float* __restrict__ out)
{
    extern __shared__ float sm[];
    const int tid  = threadIdx.x;
    const int wid  = tid >> 5;
    const int lane = tid & 31;
    const int g    = lane >> 2, t = lane & 3;
    const int b0   = blockIdx.x * BPB;
    const float4* X4 = (const float4*)X;

    stage_x(sm, X4, b0, 0, 0, tid);
    stage_x(sm, X4, b0, 1, 1, tid);

    // ---- prepack bf16 W fragments (proven layout) ----
    uint2* Bp = (uint2*)(sm + BPOFF);
    for (int i = tid; i < 1024; i += NTHR) {
        int kt = i >> 7, rem = i & 127, nt = rem >> 5, ln = rem & 31;
        int n  = nt * 8 + (ln >> 2);
        int k0 = kt * 16 + (ln & 3) * 2;
        float w0 = 0.f, w1 = 0.f, w2 = 0.f, w3 = 0.f;
        if (n < LNUM) {
            w0 = W[n * DDIM + k0];     w1 = W[n * DDIM + k0 + 1];
            w2 = W[n * DDIM + k0 + 8]; w3 = W[n * DDIM + k0 + 9];
        }
        Bp[i] = make_uint2(bfpack(w0, w1), bfpack(w2, w3));
    }
    float* Tsm = sm + TSOFF;
    for (int i = tid; i < LNUM * LNUM; i += NTHR) Tsm[i] = T[i];
    if (tid == 0) {
        const int* y32 = (const int*)Yv;
        int nz = 0;
        for (int i = 1; i < 128; i += 2) nz |= y32[i];
        ((int*)sm)[FLGOFF] = (nz == 0) ? 1 : 0;
    }
    __syncthreads();

    // ---- preload Y labels ----
    {
        const bool is64i = ((int*)sm)[FLGOFF] != 0;
        int* Ys = (int*)sm + YSOFF;
        if (is64i) {
            const long long* Y64 = (const long long*)Yv;
            #pragma unroll
            for (int u = 0; u < BPB * MLEN / NTHR; u++) {
                int i = tid + u * NTHR;
                Ys[i] = (int)Y64[(size_t)b0 * MLEN + i];
            }
        } else {
            const int* Y32 = (const int*)Yv;
            #pragma unroll
            for (int u = 0; u < BPB * MLEN / NTHR; u++) {
                int i = tid + u * NTHR;
                Ys[i] = Y32[(size_t)b0 * MLEN + i];
            }
        }
    }

    // ---- expT B-fragments in registers (constant): BT[kc][nt] ----
    uint2 BT[2][4];
    #pragma unroll
    for (int kc = 0; kc < 2; kc++)
        #pragma unroll
        for (int nt = 0; nt < 4; nt++) {
            int j = nt * 8 + g;
            float v0 = 0.f, v1 = 0.f, v2 = 0.f, v3 = 0.f;
            if (j < LNUM) {
                int k0 = kc * 16 + 2 * t;
                if (k0     < LNUM) v0 = __expf(Tsm[(k0)     * LNUM + j]);
                if (k0 + 1 < LNUM) v1 = __expf(Tsm[(k0 + 1) * LNUM + j]);
                if (k0 + 8 < LNUM) v2 = __expf(Tsm[(k0 + 8) * LNUM + j]);
                if (k0 + 9 < LNUM) v3 = __expf(Tsm[(k0 + 9) * LNUM + j]);
            }
            BT[kc][nt] = make_uint2(bfpack(v0, v1), bfpack(v2, v3));
        }
    __syncthreads();

    const int* Ys = (int*)sm + YSOFF;
    const int wa = wid * 16 + g;       // word of row g
    const int wb = wa + 8;             // word of row g+8

    float a[4][4];
    #pragma unroll
    for (int nt = 0; nt < 4; nt++)
        #pragma unroll
        for (int r = 0; r < 4; r++) a[nt][r] = 1.0f;

    float node = 0.f, node8 = 0.f, edge = 0.f, edge8 = 0.f;
    float csc = 0.f, csc8 = 0.f, logz = 0.f, logz8 = 0.f;

    for (int s = 0; s < MLEN; s++) {
        const int buf = s & 1;

        if (s < MLEN - 1) asm volatile("cp.async.wait_group 1;" ::: "memory");
        else              asm volatile("cp.async.wait_group 0;" ::: "memory");
        __syncthreads();

        // ---- emission MMA: rows [wid*16, +16) x N=32, K=128 ----
        float e[4][4];
        #pragma unroll
        for (int nt = 0; nt < 4; nt++)
            #pragma unroll
            for (int r = 0; r < 4; r++) e[nt][r] = 0.f;
        {
            const float* Xb = sm + XOFF(buf) + (wid * 16) * XSTR;
            #pragma unroll
            for (int kt = 0; kt < 8; kt++) {
                const float* xp = Xb + g * XSTR + kt * 16 + t * 2;
                float2 v0 = *(const float2*)(xp);
                float2 v2 = *(const float2*)(xp + 8);
                float2 v1 = *(const float2*)(xp + 8 * XSTR);
                float2 v3 = *(const float2*)(xp + 8 * XSTR + 8);
                uint32_t a0 = bfpack(v0.x, v0.y);
                uint32_t a1 = bfpack(v1.x, v1.y);
                uint32_t a2 = bfpack(v2.x, v2.y);
                uint32_t a3 = bfpack(v3.x, v3.y);
                const uint2* bp = Bp + kt * 128 + lane;
                uint2 bf0 = bp[0];
                uint2 bf1 = bp[32];
                uint2 bf2 = bp[64];
                uint2 bf3 = bp[96];
                mma_bf16(e[0], a0, a1, a2, a3, bf0.x, bf0.y);
                mma_bf16(e[1], a0, a1, a2, a3, bf1.x, bf1.y);
                mma_bf16(e[2], a0, a1, a2, a3, bf2.x, bf2.y);
                mma_bf16(e[3], a0, a1, a2, a3, bf3.x, bf3.y);
            }
        }
        __syncthreads();                 // all warps done reading buf
        if (s + 2 < MLEN) stage_x(sm, X4, b0, s + 2, buf, tid);

        // ---- node potential: predicated pick from acc layout ----
        int ya = Ys[wa * MLEN + s];
        int yb = Ys[wb * MLEN + s];
        #pragma unroll
        for (int nt = 0; nt < 4; nt++) {
            #pragma unroll
            for (int r = 0; r < 2; r++) {
                int col = nt * 8 + 2 * t + r;
                if (ya == col) node  += e[nt][r];
                if (yb == col) node8 += e[nt][2 + r];
            }
        }

        // ---- beta = a * exp(e) ----
        float bt[4][4];
        #pragma unroll
        for (int nt = 0; nt < 4; nt++)
            #pragma unroll
            for (int r = 0; r < 4; r++) bt[nt][r] = a[nt][r] * __expf(e[nt][r]);

        if (s + 1 < MLEN) {
            if (t == 0) {
                int yna = Ys[wa * MLEN + s + 1];
                int ynb = Ys[wb * MLEN + s + 1];
                edge  += Tsm[ya * LNUM + yna];
                edge8 += Tsm[yb * LNUM + ynb];
            }
            // ---- recurrence MMA: sv[16x32] = beta[16x32] x expT[32x32] ----
            float sv[4][4];
            #pragma unroll
            for (int nt = 0; nt < 4; nt++)
                #pragma unroll
                for (int r = 0; r < 4; r++) sv[nt][r] = 0.f;
            #pragma unroll
            for (int kc = 0; kc < 2; kc++) {
                uint32_t a0 = bfpack(bt[2 * kc][0],     bt[2 * kc][1]);
                uint32_t a1 = bfpack(bt[2 * kc][2],     bt[2 * kc][3]);
                uint32_t a2 = bfpack(bt[2 * kc + 1][0], bt[2 * kc + 1][1]);
                uint32_t a3 = bfpack(bt[2 * kc + 1][2], bt[2 * kc + 1][3]);
                #pragma unroll
                for (int nt = 0; nt < 4; nt++)
                    mma_bf16(sv[nt], a0, a1, a2, a3, BT[kc][nt].x, BT[kc][nt].y);
            }
            // ---- row max via quad butterfly ----
            float mg = sv[0][0], m8 = sv[0][2];
            #pragma unroll
            for (int nt = 0; nt < 4; nt++) {
                mg = fmaxf(mg, fmaxf(sv[nt][0], sv[nt][1]));
                m8 = fmaxf(m8, fmaxf(sv[nt][2], sv[nt][3]));
            }
            mg = fmaxf(mg, __shfl_xor_sync(0xffffffffu, mg, 1));
            mg = fmaxf(mg, __shfl_xor_sync(0xffffffffu, mg, 2));
            m8 = fmaxf(m8, __shfl_xor_sync(0xffffffffu, m8, 1));
            m8 = fmaxf(m8, __shfl_xor_sync(0xffffffffu, m8, 2));
            float inv  = __fdividef(1.0f, mg);
            float inv8 = __fdividef(1.0f, m8);
            #pragma unroll
            for (int nt = 0; nt < 4; nt++) {
                a[nt][0] = sv[nt][0] * inv;
                a[nt][1] = sv[nt][1] * inv;
                a[nt][2] = sv[nt][2] * inv8;
                a[nt][3] = sv[nt][3] * inv8;
            }
            csc  += __logf(mg);
            csc8 += __logf(m8);
        } else {
            float ssum = 0.f, ssum8 = 0.f;
            #pragma unroll
            for (int nt = 0; nt < 4; nt++) {
                ssum  += bt[nt][0] + bt[nt][1];
                ssum8 += bt[nt][2] + bt[nt][3];
            }
            ssum  += __shfl_xor_sync(0xffffffffu, ssum, 1);
            ssum  += __shfl_xor_sync(0xffffffffu, ssum, 2);
            ssum8 += __shfl_xor_sync(0xffffffffu, ssum8, 1);
            ssum8 += __shfl_xor_sync(0xffffffffu, ssum8, 2);
            logz  = csc  + __logf(ssum);
            logz8 = csc8 + __logf(ssum8);
        }
    }

    // ---- reduction: per-word contribution = logz - node - edge ----
    float val = -(node + node8);
    if (t == 0) val += (logz - edge) + (logz8 - edge8);
    #pragma unroll
    for (int o = 16; o; o >>= 1) val += __shfl_xor_sync(0xffffffffu, val, o);
    float* red = sm + REDOFF;
    if (lane == 0) red[wid] = val;
    __syncthreads();

    __shared__ int s_last;
    if (tid == 0) {
        g_partials[blockIdx.x] = red[0] + red[1] + red[2] + red[3];
        __threadfence();
        unsigned int old = atomicAdd(&g_count, 1u);
        s_last = (old == (unsigned)(gridDim.x - 1)) ? 1 : 0;
    }
    __syncthreads();
    if (s_last && tid < 32) {
        __threadfence();
        const volatile float* gp = (const volatile float*)g_partials;
        float v = 0.f;
        #pragma unroll
        for (int i = 0; i < GRID / 32; i++) v += gp[lane + i * 32];  // fixed order
        #pragma unroll
        for (int o = 16; o; o >>= 1) v += __shfl_xor_sync(0xffffffffu, v, o);
        if (lane == 0) { out[0] = v; g_count = 0; }
    }
}

extern "C" void kernel_launch(void* const* d_in, const int* in_sizes, int n_in,
                              void* d_out, int out_size)
{
    const float* X = (const float*)d_in[0];
    const void*  Y = d_in[1];
    const float* W = (const float*)d_in[2];
    const float* T = (const float*)d_in[3];

    cudaFuncSetAttribute(crf_main, cudaFuncAttributeMaxDynamicSharedMemorySize, SMEM_BYTES);
    crf_main<<<GRID, NTHR, SMEM_BYTES>>>(X, Y, W, T, (float*)d_out);
}

// round 11
// speedup vs baseline: 1.9814x; 1.0355x over previous
#include <cuda_runtime.h>
#include <cstdint>

#define MLEN  16
#define DDIM  128
#define LNUM  26
#define BPB   64      // words per block
#define NTHR  256     // 8 warps: 4 row-groups x 2 K-halves
#define GRID  256
#define XSTR  136     // padded floats per X row
#define NBUF  2
#define PSTR  20      // floats per partial slot (bank-conflict-free)

// ---- smem layout (float indices) ----
#define XS_F    (BPB * XSTR)                 // 8704 per buffer
#define XOFF(b) ((b) * XS_F)
#define BPOFF   (NBUF * XS_F)                // 17408: Bp 1024 uint2 = 2048 floats
#define PSOFF   (BPOFF + 2048)               // 19456: partials 128 slots x 20 = 2560
#define TSOFF   (PSOFF + 128 * PSTR)         // 22016: raw T 676
#define YSOFF   (TSOFF + LNUM * LNUM)        // 22692: Y labels 64*16
#define REDOFF  (YSOFF + BPB * MLEN)         // 23716
#define FLGOFF  (REDOFF + 4)
#define SMEM_F  (FLGOFF + 4)
#define SMEM_BYTES (SMEM_F * 4)              // ~92.7 KB -> 2 blocks/SM (16 warps)

__device__ float g_partials[GRID];
__device__ unsigned int g_count;

static __device__ __forceinline__ void cp16(uint32_t dst, const void* src){
    asm volatile("cp.async.cg.shared.global [%0], [%1], 16;" :: "r"(dst), "l"(src));
}
static __device__ __forceinline__ uint32_t bfpack(float lo, float hi){
    uint32_t r; asm("cvt.rn.bf16x2.f32 %0, %1, %2;" : "=r"(r) : "f"(hi), "f"(lo)); return r;
}
static __device__ __forceinline__ void mma_bf16(float* d, uint32_t a0, uint32_t a1, uint32_t a2, uint32_t a3,
                                                uint32_t b0, uint32_t b1){
    asm volatile("mma.sync.aligned.m16n8k16.row.col.f32.bf16.bf16.f32 "
                 "{%0,%1,%2,%3}, {%4,%5,%6,%7}, {%8,%9}, {%0,%1,%2,%3};"
                 : "+f"(d[0]), "+f"(d[1]), "+f"(d[2]), "+f"(d[3])
                 : "r"(a0), "r"(a1), "r"(a2), "r"(a3), "r"(b0), "r"(b1));
}

static __device__ __forceinline__ void stage_x(float* sm, const float4* X4, int b0, int s, int buf, int tid){
    uint32_t base = (uint32_t)__cvta_generic_to_shared(sm + XOFF(buf));
    #pragma unroll
    for (int u = 0; u < BPB * 32 / NTHR; u++) {     // 8 per thread
        int v = tid + u * NTHR;
        int i = v >> 5, f = v & 31;
        uint32_t dst = base + (uint32_t)(i * XSTR + f * 4) * 4u;
        cp16(dst, X4 + ((size_t)(b0 + i) * MLEN + s) * 32 + f);
    }
    asm volatile("cp.async.commit_group;" ::: "memory");
}

__global__ __launch_bounds__(NTHR, 2)
void crf_main(const float* __restrict__ X, const void* __restrict__ Yv,
              const float* __restrict__ W, const float* __restrict__ T,
              float* __restrict__ out)
{
    extern __shared__ float sm[];
    const int tid  = threadIdx.x;
    const int wid  = tid >> 5;
    const int lane = tid & 31;
    const int g    = lane >> 2, t = lane & 3;
    const int wh   = wid & 3;          // row group
    const int kh   = wid >> 2;         // K half (0 or 1)
    const int b0   = blockIdx.x * BPB;
    const float4* X4 = (const float4*)X;

    stage_x(sm, X4, b0, 0, 0, tid);
    stage_x(sm, X4, b0, 1, 1, tid);

    // ---- prepack bf16 W fragments ----
    uint2* Bp = (uint2*)(sm + BPOFF);
    #pragma unroll
    for (int u = 0; u < 4; u++) {
        int i = tid + u * NTHR;
        int kt = i >> 7, rem = i & 127, nt = rem >> 5, ln = rem & 31;
        int n  = nt * 8 + (ln >> 2);
        int k0 = kt * 16 + (ln & 3) * 2;
        float w0 = 0.f, w1 = 0.f, w2 = 0.f, w3 = 0.f;
        if (n < LNUM) {
            w0 = W[n * DDIM + k0];     w1 = W[n * DDIM + k0 + 1];
            w2 = W[n * DDIM + k0 + 8]; w3 = W[n * DDIM + k0 + 9];
        }
        Bp[i] = make_uint2(bfpack(w0, w1), bfpack(w2, w3));
    }
    float* Tsm = sm + TSOFF;
    for (int i = tid; i < LNUM * LNUM; i += NTHR) Tsm[i] = T[i];
    if (tid == 0) {
        const int* y32 = (const int*)Yv;
        int nz = 0;
        for (int i = 1; i < 128; i += 2) nz |= y32[i];
        ((int*)sm)[FLGOFF] = (nz == 0) ? 1 : 0;
    }
    __syncthreads();

    // ---- preload Y labels ----
    {
        const bool is64i = ((int*)sm)[FLGOFF] != 0;
        int* Ys = (int*)sm + YSOFF;
        if (is64i) {
            const long long* Y64 = (const long long*)Yv;
            #pragma unroll
            for (int u = 0; u < BPB * MLEN / NTHR; u++) {
                int i = tid + u * NTHR;
                Ys[i] = (int)Y64[(size_t)b0 * MLEN + i];
            }
        } else {
            const int* Y32 = (const int*)Yv;
            #pragma unroll
            for (int u = 0; u < BPB * MLEN / NTHR; u++) {
                int i = tid + u * NTHR;
                Ys[i] = Y32[(size_t)b0 * MLEN + i];
            }
        }
    }

    // ---- expT B-fragments in registers (only used by kh==0 warps) ----
    uint2 BT[2][4];
    #pragma unroll
    for (int kc = 0; kc < 2; kc++)
        #pragma unroll
        for (int nt = 0; nt < 4; nt++) {
            int j = nt * 8 + g;
            float v0 = 0.f, v1 = 0.f, v2 = 0.f, v3 = 0.f;
            if (j < LNUM) {
                int k0 = kc * 16 + 2 * t;
                if (k0     < LNUM) v0 = __expf(Tsm[(k0)     * LNUM + j]);
                if (k0 + 1 < LNUM) v1 = __expf(Tsm[(k0 + 1) * LNUM + j]);
                if (k0 + 8 < LNUM) v2 = __expf(Tsm[(k0 + 8) * LNUM + j]);
                if (k0 + 9 < LNUM) v3 = __expf(Tsm[(k0 + 9) * LNUM + j]);
            }
            BT[kc][nt] = make_uint2(bfpack(v0, v1), bfpack(v2, v3));
        }
    __syncthreads();

    const int* Ys = (int*)sm + YSOFF;
    float* Psm = sm + PSOFF + (wh * 32 + lane) * PSTR;   // this thread's partial slot

    const int wa = wh * 16 + g;
    const int wb = wa + 8;

    float a[4][4];
    #pragma unroll
    for (int nt = 0; nt < 4; nt++)
        #pragma unroll
        for (int r = 0; r < 4; r++) a[nt][r] = 1.0f;

    float node = 0.f, node8 = 0.f, edge = 0.f, edge8 = 0.f;
    float csc = 0.f, csc8 = 0.f, logz = 0.f, logz8 = 0.f;

    for (int s = 0; s < MLEN; s++) {
        const int buf = s & 1;

        if (s < MLEN - 1) asm volatile("cp.async.wait_group 1;" ::: "memory");
        else              asm volatile("cp.async.wait_group 0;" ::: "memory");
        __syncthreads();   // X(s) visible; Psm(s-1) consumed

        // ---- emission half-GEMM: rows [wh*16,+16) x N=32, K-half kh ----
        float e[4][4];
        #pragma unroll
        for (int nt = 0; nt < 4; nt++)
            #pragma unroll
            for (int r = 0; r < 4; r++) e[nt][r] = 0.f;
        {
            const float* Xb = sm + XOFF(buf) + (wh * 16) * XSTR;
            #pragma unroll
            for (int kl = 0; kl < 4; kl++) {
                const int kt = kh * 4 + kl;
                const float* xp = Xb + g * XSTR + kt * 16 + t * 2;
                float2 v0 = *(const float2*)(xp);
                float2 v2 = *(const float2*)(xp + 8);
                float2 v1 = *(const float2*)(xp + 8 * XSTR);
                float2 v3 = *(const float2*)(xp + 8 * XSTR + 8);
                uint32_t a0 = bfpack(v0.x, v0.y);
                uint32_t a1 = bfpack(v1.x, v1.y);
                uint32_t a2 = bfpack(v2.x, v2.y);
                uint32_t a3 = bfpack(v3.x, v3.y);
                const uint2* bp = Bp + kt * 128 + lane;
                uint2 bf0 = bp[0];
                uint2 bf1 = bp[32];
                uint2 bf2 = bp[64];
                uint2 bf3 = bp[96];
                mma_bf16(e[0], a0, a1, a2, a3, bf0.x, bf0.y);
                mma_bf16(e[1], a0, a1, a2, a3, bf1.x, bf1.y);
                mma_bf16(e[2], a0, a1, a2, a3, bf2.x, bf2.y);
                mma_bf16(e[3], a0, a1, a2, a3, bf3.x, bf3.y);
            }
        }
        // upper-half warps publish partials
        if (kh == 1) {
            #pragma unroll
            for (int nt = 0; nt < 4; nt++)
                *(float4*)&Psm[nt * 4] = make_float4(e[nt][0], e[nt][1], e[nt][2], e[nt][3]);
        }
        __syncthreads();   // partials visible; X(buf) fully consumed

        if (s + 2 < MLEN) stage_x(sm, X4, b0, s + 2, buf, tid);

        if (kh == 0) {
            // ---- combine K halves ----
            #pragma unroll
            for (int nt = 0; nt < 4; nt++) {
                float4 p = *(const float4*)&Psm[nt * 4];
                e[nt][0] += p.x; e[nt][1] += p.y; e[nt][2] += p.z; e[nt][3] += p.w;
            }

            // ---- node potential ----
            int ya = Ys[wa * MLEN + s];
            int yb = Ys[wb * MLEN + s];
            #pragma unroll
            for (int nt = 0; nt < 4; nt++) {
                #pragma unroll
                for (int r = 0; r < 2; r++) {
                    int col = nt * 8 + 2 * t + r;
                    if (ya == col) node  += e[nt][r];
                    if (yb == col) node8 += e[nt][2 + r];
                }
            }

            // ---- beta = a * exp(e) ----
            float bt[4][4];
            #pragma unroll
            for (int nt = 0; nt < 4; nt++)
                #pragma unroll
                for (int r = 0; r < 4; r++) bt[nt][r] = a[nt][r] * __expf(e[nt][r]);

            if (s + 1 < MLEN) {
                if (t == 0) {
                    int yna = Ys[wa * MLEN + s + 1];
                    int ynb = Ys[wb * MLEN + s + 1];
                    edge  += Tsm[ya * LNUM + yna];
                    edge8 += Tsm[yb * LNUM + ynb];
                }
                // ---- recurrence MMA ----
                float sv[4][4];
                #pragma unroll
                for (int nt = 0; nt < 4; nt++)
                    #pragma unroll
                    for (int r = 0; r < 4; r++) sv[nt][r] = 0.f;
                #pragma unroll
                for (int kc = 0; kc < 2; kc++) {
                    uint32_t a0 = bfpack(bt[2 * kc][0],     bt[2 * kc][1]);
                    uint32_t a1 = bfpack(bt[2 * kc][2],     bt[2 * kc][3]);
                    uint32_t a2 = bfpack(bt[2 * kc + 1][0], bt[2 * kc + 1][1]);
                    uint32_t a3 = bfpack(bt[2 * kc + 1][2], bt[2 * kc + 1][3]);
                    #pragma unroll
                    for (int nt = 0; nt < 4; nt++)
                        mma_bf16(sv[nt], a0, a1, a2, a3, BT[kc][nt].x, BT[kc][nt].y);
                }
                // ---- row max + renormalize ----
                float mg = sv[0][0], m8 = sv[0][2];
                #pragma unroll
                for (int nt = 0; nt < 4; nt++) {
                    mg = fmaxf(mg, fmaxf(sv[nt][0], sv[nt][1]));
                    m8 = fmaxf(m8, fmaxf(sv[nt][2], sv[nt][3]));
                }
                mg = fmaxf(mg, __shfl_xor_sync(0xffffffffu, mg, 1));
                mg = fmaxf(mg, __shfl_xor_sync(0xffffffffu, mg, 2));
                m8 = fmaxf(m8, __shfl_xor_sync(0xffffffffu, m8, 1));
                m8 = fmaxf(m8, __shfl_xor_sync(0xffffffffu, m8, 2));
                float inv  = __fdividef(1.0f, mg);
                float inv8 = __fdividef(1.0f, m8);
                #pragma unroll
                for (int nt = 0; nt < 4; nt++) {
                    a[nt][0] = sv[nt][0] * inv;
                    a[nt][1] = sv[nt][1] * inv;
                    a[nt][2] = sv[nt][2] * inv8;
                    a[nt][3] = sv[nt][3] * inv8;
                }
                csc  += __logf(mg);
                csc8 += __logf(m8);
            } else {
                float ssum = 0.f, ssum8 = 0.f;
                #pragma unroll
                for (int nt = 0; nt < 4; nt++) {
                    ssum  += bt[nt][0] + bt[nt][1];
                    ssum8 += bt[nt][2] + bt[nt][3];
                }
                ssum  += __shfl_xor_sync(0xffffffffu, ssum, 1);
                ssum  += __shfl_xor_sync(0xffffffffu, ssum, 2);
                ssum8 += __shfl_xor_sync(0xffffffffu, ssum8, 1);
                ssum8 += __shfl_xor_sync(0xffffffffu, ssum8, 2);
                logz  = csc  + __logf(ssum);
                logz8 = csc8 + __logf(ssum8);
            }
        }
    }

    // ---- reduction (kh==0 warps hold values) ----
    float val = 0.f;
    if (kh == 0) {
        val = -(node + node8);
        if (t == 0) val += (logz - edge) + (logz8 - edge8);
    }
    #pragma unroll
    for (int o = 16; o; o >>= 1) val += __shfl_xor_sync(0xffffffffu, val, o);
    float* red = sm + REDOFF;
    if (wid < 4 && lane == 0) red[wid] = val;
    __syncthreads();

    __shared__ int s_last;
    if (tid == 0) {
        g_partials[blockIdx.x] = red[0] + red[1] + red[2] + red[3];
        __threadfence();
        unsigned int old = atomicAdd(&g_count, 1u);
        s_last = (old == (unsigned)(gridDim.x - 1)) ? 1 : 0;
    }
    __syncthreads();
    if (s_last && tid < 32) {
        __threadfence();
        const volatile float* gp = (const volatile float*)g_partials;
        float v = 0.f;
        #pragma unroll
        for (int i = 0; i < GRID / 32; i++) v += gp[lane + i * 32];  // fixed order
        #pragma unroll
        for (int o = 16; o; o >>= 1) v += __shfl_xor_sync(0xffffffffu, v, o);
        if (lane == 0) { out[0] = v; g_count = 0; }
    }
}

extern "C" void kernel_launch(void* const* d_in, const int* in_sizes, int n_in,
                              void* d_out, int out_size)
{
    const float* X = (const float*)d_in[0];
    const void*  Y = d_in[1];
    const float* W = (const float*)d_in[2];
    const float* T = (const float*)d_in[3];

    cudaFuncSetAttribute(crf_main, cudaFuncAttributeMaxDynamicSharedMemorySize, SMEM_BYTES);
    crf_main<<<GRID, NTHR, SMEM_BYTES>>>(X, Y, W, T, (float*)d_out);
}